// round 7
// baseline (speedup 1.0000x reference)
#include <cuda_runtime.h>
#include <cuda_bf16.h>
#include <cstdint>

// Problem constants (from reference)
#define B_  8
#define L_  2048
#define P_  576
#define V_  32000
#define D_  2560
#define T_  (L_ - 1 + P_)      // 2623
#define IGNORE_INDEX_ (-100)

// Write-through float4 store: output stream takes no L2 lines.
__device__ __forceinline__ void stwt4(float4* p, float4 v) {
    asm volatile("st.global.wt.v4.f32 [%0], {%1,%2,%3,%4};"
                 :: "l"(p), "f"(v.x), "f"(v.y), "f"(v.z), "f"(v.w)
                 : "memory");
}

// 32-byte read-only load with L2 evict_last priority (sm_103a requires
// v8.b32 width for this modifier). Embed-table rows are the reused working
// set; give them last-eviction priority in L2.
struct F8 { float4 a, b; };
__device__ __forceinline__ F8 ldg_el8(const float* p) {
    F8 v;
    asm volatile(
        "ld.global.nc.L2::evict_last.v8.b32 {%0,%1,%2,%3,%4,%5,%6,%7}, [%8];"
        : "=f"(v.a.x), "=f"(v.a.y), "=f"(v.a.z), "=f"(v.a.w),
          "=f"(v.b.x), "=f"(v.b.y), "=f"(v.b.z), "=f"(v.b.w)
        : "l"(p));
    return v;
}

// One block per output row (b, t). 128 threads.
// Embed path: 320 x 32B chunks -> 2 unconditional + 1 predicated (tid<64)
// evict_last loads per thread, front-batched.
// Image path: 5 x float4 __ldcs per thread (read-once stream).
// All payload stores write-through (no L2 footprint).
__global__ void __launch_bounds__(128)
splice_kernel(const float* __restrict__ embed_table,     // [V, D]
              const float* __restrict__ image_features,  // [B, P, D]
              const int*   __restrict__ input_ids,       // [B, L]
              const int*   __restrict__ labels,          // [B, L]
              const int*   __restrict__ img_pos,         // [B]
              float* __restrict__ out)
{
    const int row = blockIdx.x;           // 0 .. B*T-1
    const int b = row / T_;
    const int t = row - b * T_;

    const int pos = img_pos[b];
    const bool is_img = (t >= pos) && (t < pos + P_);

    int tok_idx = (t < pos) ? t : (t - P_ + 1);
    tok_idx = max(0, min(tok_idx, L_ - 1));

    float4* __restrict__ dst =
        reinterpret_cast<float4*>(out + (long long)row * D_);

    const int tid = threadIdx.x;

    if (is_img) {
        const int img_idx = max(0, min(t - pos, P_ - 1));
        const float4* __restrict__ src = reinterpret_cast<const float4*>(
            image_features + ((long long)b * P_ + img_idx) * D_);
        float4 v0 = __ldcs(src + tid);
        float4 v1 = __ldcs(src + tid + 128);
        float4 v2 = __ldcs(src + tid + 256);
        float4 v3 = __ldcs(src + tid + 384);
        float4 v4 = __ldcs(src + tid + 512);
        stwt4(dst + tid,       v0);
        stwt4(dst + tid + 128, v1);
        stwt4(dst + tid + 256, v2);
        stwt4(dst + tid + 384, v3);
        stwt4(dst + tid + 512, v4);
    } else {
        const int tok = input_ids[b * L_ + tok_idx];
        const float* __restrict__ src = embed_table + (long long)tok * D_;
        // 32B chunks: thread covers chunk tid, tid+128, and (tid<64) tid+256
        const bool has2 = (tid < 64);
        F8 v0 = ldg_el8(src + (tid        ) * 8);
        F8 v1 = ldg_el8(src + (tid + 128  ) * 8);
        F8 v2;
        if (has2) v2 = ldg_el8(src + (tid + 256) * 8);
        // chunk c maps to float4 slots 2c and 2c+1
        stwt4(dst + 2 * tid,            v0.a);
        stwt4(dst + 2 * tid + 1,        v0.b);
        stwt4(dst + 2 * (tid + 128),     v1.a);
        stwt4(dst + 2 * (tid + 128) + 1, v1.b);
        if (has2) {
            stwt4(dst + 2 * (tid + 256),     v2.a);
            stwt4(dst + 2 * (tid + 256) + 1, v2.b);
        }
    }

    if (tid == 0) {
        float* tails = out + (long long)B_ * T_ * D_;
        // new_labels
        tails[row] = is_img ? (float)IGNORE_INDEX_
                            : (float)labels[b * L_ + tok_idx];
        // attention_mask (all true)
        tails[(long long)B_ * T_ + row] = 1.0f;
        // position_ids (iota over T)
        tails[2LL * B_ * T_ + row] = (float)t;
    }
}

extern "C" void kernel_launch(void* const* d_in, const int* in_sizes, int n_in,
                              void* d_out, int out_size)
{
    const float* embed_table    = (const float*)d_in[0];
    const float* image_features = (const float*)d_in[1];
    const int*   input_ids      = (const int*)  d_in[2];
    const int*   labels         = (const int*)  d_in[3];
    const int*   img_pos        = (const int*)  d_in[4];
    float* out = (float*)d_out;

    const int n_rows = B_ * T_;   // 20984
    splice_kernel<<<n_rows, 128>>>(embed_table, image_features,
                                   input_ids, labels, img_pos, out);
}

// round 8
// speedup vs baseline: 1.0111x; 1.0111x over previous
#include <cuda_runtime.h>
#include <cuda_bf16.h>
#include <cstdint>

// Problem constants (from reference)
#define B_  8
#define L_  2048
#define P_  576
#define V_  32000
#define D_  2560
#define T_  (L_ - 1 + P_)      // 2623
#define IGNORE_INDEX_ (-100)

// Write-through float4 store: output stream takes no L2 lines.
__device__ __forceinline__ void stwt4(float4* p, float4 v) {
    asm volatile("st.global.wt.v4.f32 [%0], {%1,%2,%3,%4};"
                 :: "l"(p), "f"(v.x), "f"(v.y), "f"(v.z), "f"(v.w)
                 : "memory");
}

// One block per output row (b, t). 128 threads, 640 float4 per row ->
// exactly 5 unconditional float4 per thread, loads front-batched.
//
// Cache policy:
//   embed_table   -> __ldcg : L2-only (reuse is cross-SM; skip L1 fills)
//   image_features-> __ldcs : read-once streaming
//   output        -> st.wt  : no L2 footprint (keeps embed rows resident)
__global__ void __launch_bounds__(128)
splice_kernel(const float* __restrict__ embed_table,     // [V, D]
              const float* __restrict__ image_features,  // [B, P, D]
              const int*   __restrict__ input_ids,       // [B, L]
              const int*   __restrict__ labels,          // [B, L]
              const int*   __restrict__ img_pos,         // [B]
              float* __restrict__ out)
{
    const int row = blockIdx.x;           // 0 .. B*T-1
    const int b = row / T_;
    const int t = row - b * T_;

    const int pos = img_pos[b];
    const bool is_img = (t >= pos) && (t < pos + P_);

    int tok_idx = (t < pos) ? t : (t - P_ + 1);
    tok_idx = max(0, min(tok_idx, L_ - 1));

    float4* __restrict__ dst =
        reinterpret_cast<float4*>(out + (long long)row * D_);

    const int tid = threadIdx.x;

    if (is_img) {
        const int img_idx = max(0, min(t - pos, P_ - 1));
        const float4* __restrict__ src = reinterpret_cast<const float4*>(
            image_features + ((long long)b * P_ + img_idx) * D_);
        float4 v0 = __ldcs(src + tid);
        float4 v1 = __ldcs(src + tid + 128);
        float4 v2 = __ldcs(src + tid + 256);
        float4 v3 = __ldcs(src + tid + 384);
        float4 v4 = __ldcs(src + tid + 512);
        stwt4(dst + tid,       v0);
        stwt4(dst + tid + 128, v1);
        stwt4(dst + tid + 256, v2);
        stwt4(dst + tid + 384, v3);
        stwt4(dst + tid + 512, v4);
    } else {
        const int tok = input_ids[b * L_ + tok_idx];
        const float4* __restrict__ src = reinterpret_cast<const float4*>(
            embed_table + (long long)tok * D_);
        float4 v0 = __ldcg(src + tid);
        float4 v1 = __ldcg(src + tid + 128);
        float4 v2 = __ldcg(src + tid + 256);
        float4 v3 = __ldcg(src + tid + 384);
        float4 v4 = __ldcg(src + tid + 512);
        stwt4(dst + tid,       v0);
        stwt4(dst + tid + 128, v1);
        stwt4(dst + tid + 256, v2);
        stwt4(dst + tid + 384, v3);
        stwt4(dst + tid + 512, v4);
    }

    if (tid == 0) {
        float* tails = out + (long long)B_ * T_ * D_;
        // new_labels
        tails[row] = is_img ? (float)IGNORE_INDEX_
                            : (float)labels[b * L_ + tok_idx];
        // attention_mask (all true)
        tails[(long long)B_ * T_ + row] = 1.0f;
        // position_ids (iota over T)
        tails[2LL * B_ * T_ + row] = (float)t;
    }
}

extern "C" void kernel_launch(void* const* d_in, const int* in_sizes, int n_in,
                              void* d_out, int out_size)
{
    const float* embed_table    = (const float*)d_in[0];
    const float* image_features = (const float*)d_in[1];
    const int*   input_ids      = (const int*)  d_in[2];
    const int*   labels         = (const int*)  d_in[3];
    const int*   img_pos        = (const int*)  d_in[4];
    float* out = (float*)d_out;

    const int n_rows = B_ * T_;   // 20984
    splice_kernel<<<n_rows, 128>>>(embed_table, image_features,
                                   input_ids, labels, img_pos, out);
}